// round 2
// baseline (speedup 1.0000x reference)
#include <cuda_runtime.h>
#include <cstdint>

#define NB_B 8192
#define LOD 60
#define LSD 120
#define AD 10
#define NB 15
#define HH 60
#define BT 32
#define YD 20
#define RPT 3
#define NT (BT*YD)
#define PAD 33

typedef unsigned long long u64;

// ---- scratch (device globals; no allocation) ----
__device__ float4 g_tmb[LOD * 7 * NB];        // column-packed (t11,t21,t12,t22)
__device__ float2 g_coef2[NB * NB_B];         // duplicated coef pairs, transposed [k][b]
__device__ float  g_ctl[LSD * NB_B];          // control, transposed [c][b]
__device__ float  g_tc[LSD];                  // elup1(log_noise)

// ======================= prep kernel =======================
// blocks 0..255: coef softmax + control MLP for a 32-batch tile
// blocks 256..268: pack tmb (+ tc on block 256)
#define P_PM   0        // 120*33 = 3960
#define P_LG   3960     // 15*33  = 495
#define P_ACT  4455     // 10*33  = 330
#define P_H    4785     // 60*33  = 1980
#define P_W1   6765     // 600
#define P_W2   7365     // 7200
#define P_WC   14565    // 1800
#define P_B1   16365    // 60
#define P_B2   16425    // 120
#define P_BC   16545    // 15
#define P_SMEM 16560

__global__ void __launch_bounds__(512) prep_kernel(
    const float* __restrict__ post_mean, const float* __restrict__ action,
    const float* __restrict__ tm11, const float* __restrict__ tm12,
    const float* __restrict__ tm21, const float* __restrict__ tm22,
    const float* __restrict__ log_noise,
    const float* __restrict__ w_coef, const float* __restrict__ b_coef,
    const float* __restrict__ w_c1, const float* __restrict__ b_c1,
    const float* __restrict__ w_c2, const float* __restrict__ b_c2)
{
    const int bid = blockIdx.x;
    const int tid = threadIdx.x + threadIdx.y * 32;
    if (bid >= 256) {
        if (bid == 256 && tid < LSD) {
            float x = log_noise[tid];
            g_tc[tid] = (x < 0.f) ? expf(x) : x + 1.f;
        }
        int idx = (bid - 256) * 512 + tid;
        if (idx < LOD * 7 * NB) {
            int k = idx % NB;
            int jj = (idx / NB) % 7;
            int i = idx / (NB * 7);
            int j = i + jj - 3;
            float4 v = make_float4(0.f, 0.f, 0.f, 0.f);
            if (j >= 0 && j < LOD) {
                int off = k * LOD * LOD + i * LOD + j;
                v.x = tm11[off]; v.y = tm21[off];   // column-packed!
                v.z = tm12[off]; v.w = tm22[off];
            }
            g_tmb[idx] = v;
        }
        return;
    }

    extern __shared__ float sp[];
    const int lane = threadIdx.x, yy = threadIdx.y;   // (32,16)
    const int b0 = bid * BT;

    for (int e = tid; e < BT * LSD; e += 512) {
        int bl = e / LSD, d = e % LSD;
        sp[P_PM + d * PAD + bl] = post_mean[(b0 + bl) * LSD + d];
    }
    for (int e = tid; e < BT * AD; e += 512) {
        int bl = e / AD, d = e % AD;
        sp[P_ACT + d * PAD + bl] = action[(b0 + bl) * AD + d];
    }
    for (int e = tid; e < NB * LSD; e += 512) sp[P_WC + e] = w_coef[e];
    for (int e = tid; e < HH * AD; e += 512)  sp[P_W1 + e] = w_c1[e];
    for (int e = tid; e < LSD * HH; e += 512) sp[P_W2 + e] = w_c2[e];
    for (int e = tid; e < HH; e += 512)  sp[P_B1 + e] = b_c1[e];
    for (int e = tid; e < LSD; e += 512) sp[P_B2 + e] = b_c2[e];
    for (int e = tid; e < NB; e += 512)  sp[P_BC + e] = b_coef[e];
    __syncthreads();

    if (yy < NB) {
        float lg = sp[P_BC + yy];
        #pragma unroll 4
        for (int d = 0; d < LSD; d++)
            lg = fmaf(sp[P_WC + yy * LSD + d], sp[P_PM + d * PAD + lane], lg);
        sp[P_LG + yy * PAD + lane] = lg;
    }
    #pragma unroll
    for (int t = 0; t < 4; t++) {
        int i = yy + 16 * t;
        if (i < HH) {
            float hv = sp[P_B1 + i];
            #pragma unroll
            for (int d = 0; d < AD; d++)
                hv = fmaf(sp[P_W1 + i * AD + d], sp[P_ACT + d * PAD + lane], hv);
            sp[P_H + i * PAD + lane] = fmaxf(hv, 0.f);
        }
    }
    __syncthreads();

    if (yy == 0) {
        float mx = -1e30f;
        #pragma unroll
        for (int k = 0; k < NB; k++) mx = fmaxf(mx, sp[P_LG + k * PAD + lane]);
        float ex[NB], sum = 0.f;
        #pragma unroll
        for (int k = 0; k < NB; k++) {
            ex[k] = expf(sp[P_LG + k * PAD + lane] - mx);
            sum += ex[k];
        }
        float inv = 1.f / sum;
        #pragma unroll
        for (int k = 0; k < NB; k++) sp[P_LG + k * PAD + lane] = ex[k] * inv;
    }
    __syncthreads();

    if (yy < NB) {
        float c = sp[P_LG + yy * PAD + lane];
        g_coef2[yy * NB_B + b0 + lane] = make_float2(c, c);
    }
    #pragma unroll
    for (int t = 0; t < 8; t++) {
        int c = yy + 16 * t;
        if (c < LSD) {
            float ctl = sp[P_B2 + c];
            #pragma unroll 4
            for (int m = 0; m < HH; m++)
                ctl = fmaf(sp[P_W2 + c * HH + m], sp[P_H + m * PAD + lane], ctl);
            g_ctl[c * NB_B + b0 + lane] = ctl;
        }
    }
}

// ======================= main kernel =======================
#define OFF_MU    0
#define OFF_ML    1980
#define OFF_CU    3960
#define OFF_CL    5940
#define OFF_CS2   7920
#define OFF_STAGE 9900     // 300*33
#define OFF_COEF2 19800    // float2[15*33] = 1980 floats
#define SMEM_FLOATS 21780

#define F32X2_FMA(acc, a, b) asm("fma.rn.f32x2 %0, %1, %2, %0;" : "+l"(acc) : "l"(a), "l"(b))
#define F32X2_MUL(d, a, b)   asm("mul.rn.f32x2 %0, %1, %2;" : "=l"(d) : "l"(a), "l"(b))
#define F32X2_ADD(acc, b)    asm("add.rn.f32x2 %0, %0, %1;" : "+l"(acc) : "l"(b))
#define PACK2(d, x)          asm("mov.b64 %0, {%1, %1};" : "=l"(d) : "f"(x))
#define UNPACK2(lo, hi, v)   asm("mov.b64 {%0, %1}, %2;" : "=f"(lo), "=f"(hi) : "l"(v))
#define LDS64(d, a)          asm("ld.shared.b64 %0, [%1];" : "=l"(d) : "r"(a))

__device__ __forceinline__ void combine_jj(
    u64 aU, u64 aL, int jc, int lane, const float* __restrict__ sm,
    u64& m_acc, u64& c_acc, float& ncs)
{
    float mu  = sm[OFF_MU  + jc * PAD + lane];
    float ml  = sm[OFF_ML  + jc * PAD + lane];
    float cu  = sm[OFF_CU  + jc * PAD + lane];
    float cl  = sm[OFF_CL  + jc * PAD + lane];
    float cs2 = sm[OFF_CS2 + jc * PAD + lane];
    u64 t;
    PACK2(t, mu);  F32X2_FMA(m_acc, aU, t);
    PACK2(t, ml);  F32X2_FMA(m_acc, aL, t);
    u64 sqU; F32X2_MUL(sqU, aU, aU);
    PACK2(t, cu);  F32X2_FMA(c_acc, sqU, t);
    u64 cr;  F32X2_MUL(cr, aU, aL);
    PACK2(t, cs2); F32X2_FMA(c_acc, cr, t);
    u64 sqL; F32X2_MUL(sqL, aL, aL);
    PACK2(t, cl);  F32X2_FMA(c_acc, sqL, t);
    float u0, u1, l0, l1;
    UNPACK2(u0, u1, aU); UNPACK2(l0, l1, aL);
    ncs = fmaf(u0 * u1, cu, ncs);
    ncs = fmaf(0.5f * fmaf(u0, l1, u1 * l0), cs2, ncs);
    ncs = fmaf(l0 * l1, cl, ncs);
}

__global__ void __launch_bounds__(NT, 2) acpredict_kernel(
    const float* __restrict__ post_mean, const float* __restrict__ cu_g,
    const float* __restrict__ cl_g, const float* __restrict__ cs_g,
    float* __restrict__ out)
{
    extern __shared__ float sm[];
    const int lane = threadIdx.x;
    const int y    = threadIdx.y;
    const int tid  = y * BT + lane;
    const int b0   = blockIdx.x * BT;
    const int b    = b0 + lane;

    // ---- load inputs, transposed ----
    for (int e = tid; e < BT * LSD; e += NT) {
        int bl = e / LSD, d = e % LSD;
        float v = post_mean[(b0 + bl) * LSD + d];
        if (d < LOD) sm[OFF_MU + d * PAD + bl] = v;
        else         sm[OFF_ML + (d - LOD) * PAD + bl] = v;
    }
    for (int e = tid; e < BT * LOD; e += NT) {
        int bl = e / LOD, j = e % LOD;
        sm[OFF_CU  + j * PAD + bl] = cu_g[(b0 + bl) * LOD + j];
        sm[OFF_CL  + j * PAD + bl] = cl_g[(b0 + bl) * LOD + j];
        sm[OFF_CS2 + j * PAD + bl] = 2.f * cs_g[(b0 + bl) * LOD + j];
    }
    if (tid < NB * BT) {
        int k = tid / BT, l = tid % BT;
        ((float2*)(sm + OFF_COEF2))[k * PAD + l] = g_coef2[k * NB_B + b0 + l];
    }
    __syncthreads();

    const uint32_t coefAddr =
        (uint32_t)__cvta_generic_to_shared(sm + OFF_COEF2) + (uint32_t)lane * 8u;
    const u64 ONE_LO = 0x000000003f800000ULL;   // +1 to t11 (low half of aU)
    const u64 ONE_HI = 0x3f80000000000000ULL;   // +1 to t22 (high half of aL)

    #pragma unroll
    for (int r = 0; r < RPT; r++) {
        const int i = y + YD * r;
        const ulonglong2* __restrict__ tmrow =
            reinterpret_cast<const ulonglong2*>(g_tmb) + i * 7 * NB;

        u64 m_acc = 0, c_acc = 0;
        float ncs = 0.f;

        // ---- pass A: jj = 0..3 ----
        {
            u64 aU[4] = {0,0,0,0}, aL[4] = {0,0,0,0};
            #pragma unroll
            for (int k = 0; k < NB; k++) {
                u64 c2; LDS64(c2, coefAddr + (uint32_t)(k * PAD * 8));
                #pragma unroll
                for (int jj = 0; jj < 4; jj++) {
                    ulonglong2 v = __ldg(tmrow + jj * NB + k);
                    F32X2_FMA(aU[jj], c2, v.x);
                    F32X2_FMA(aL[jj], c2, v.y);
                }
            }
            #pragma unroll
            for (int jj = 0; jj < 4; jj++) {
                if (jj == 3) { F32X2_ADD(aU[jj], ONE_LO); F32X2_ADD(aL[jj], ONE_HI); }
                int jc = min(max(i + jj - 3, 0), LOD - 1);
                combine_jj(aU[jj], aL[jj], jc, lane, sm, m_acc, c_acc, ncs);
            }
        }
        // ---- pass B: jj = 4..6 ----
        {
            u64 aU[3] = {0,0,0}, aL[3] = {0,0,0};
            #pragma unroll
            for (int k = 0; k < NB; k++) {
                u64 c2; LDS64(c2, coefAddr + (uint32_t)(k * PAD * 8));
                #pragma unroll
                for (int q = 0; q < 3; q++) {
                    ulonglong2 v = __ldg(tmrow + (4 + q) * NB + k);
                    F32X2_FMA(aU[q], c2, v.x);
                    F32X2_FMA(aL[q], c2, v.y);
                }
            }
            #pragma unroll
            for (int q = 0; q < 3; q++) {
                int jc = min(i + 4 + q - 3, LOD - 1);   // >= 1 always
                combine_jj(aU[q], aL[q], jc, lane, sm, m_acc, c_acc, ncs);
            }
        }

        float nmu, nml, ncu, ncl;
        UNPACK2(nmu, nml, m_acc);
        UNPACK2(ncu, ncl, c_acc);
        nmu += __ldg(&g_ctl[i * NB_B + b]);
        nml += __ldg(&g_ctl[(LOD + i) * NB_B + b]);
        ncu += __ldg(&g_tc[i]);
        ncl += __ldg(&g_tc[LOD + i]);

        float* s_stage = sm + OFF_STAGE;
        s_stage[(i)       * PAD + lane] = nmu;
        s_stage[(LOD + i) * PAD + lane] = nml;
        s_stage[(120 + i) * PAD + lane] = ncu;
        s_stage[(180 + i) * PAD + lane] = ncl;
        s_stage[(240 + i) * PAD + lane] = ncs;
    }
    __syncthreads();

    // ---- coalesced global stores ----
    const float* s_stage = sm + OFF_STAGE;
    for (int e = tid; e < BT * 300; e += NT) {
        int bl = e / 300, c = e % 300;
        float v = s_stage[c * PAD + bl];
        int bb = b0 + bl;
        if (c < 120)      out[bb * 120 + c] = v;
        else if (c < 180) out[NB_B * 120 + bb * 60 + (c - 120)] = v;
        else if (c < 240) out[NB_B * 180 + bb * 60 + (c - 180)] = v;
        else              out[NB_B * 240 + bb * 60 + (c - 240)] = v;
    }
}

extern "C" void kernel_launch(void* const* d_in, const int* in_sizes, int n_in,
                              void* d_out, int out_size) {
    const float* post_mean = (const float*)d_in[0];
    const float* cu        = (const float*)d_in[1];
    const float* cl        = (const float*)d_in[2];
    const float* cs        = (const float*)d_in[3];
    const float* action    = (const float*)d_in[4];
    const float* tm11      = (const float*)d_in[5];
    const float* tm12      = (const float*)d_in[6];
    const float* tm21      = (const float*)d_in[7];
    const float* tm22      = (const float*)d_in[8];
    const float* log_noise = (const float*)d_in[9];
    const float* w_coef    = (const float*)d_in[10];
    const float* b_coef    = (const float*)d_in[11];
    const float* w_c1      = (const float*)d_in[12];
    const float* b_c1      = (const float*)d_in[13];
    const float* w_c2      = (const float*)d_in[14];
    const float* b_c2      = (const float*)d_in[15];
    float* out = (float*)d_out;

    static bool attr_done = false;
    if (!attr_done) {
        cudaFuncSetAttribute(prep_kernel,
            cudaFuncAttributeMaxDynamicSharedMemorySize, P_SMEM * 4);
        cudaFuncSetAttribute(acpredict_kernel,
            cudaFuncAttributeMaxDynamicSharedMemorySize, SMEM_FLOATS * 4);
        attr_done = true;
    }

    dim3 pblk(32, 16);
    prep_kernel<<<256 + 13, pblk, P_SMEM * 4>>>(
        post_mean, action, tm11, tm12, tm21, tm22, log_noise,
        w_coef, b_coef, w_c1, b_c1, w_c2, b_c2);

    dim3 blk(BT, YD);
    acpredict_kernel<<<NB_B / BT, blk, SMEM_FLOATS * 4>>>(
        post_mean, cu, cl, cs, out);
}